// round 12
// baseline (speedup 1.0000x reference)
#include <cuda_runtime.h>
#include <cuda_fp16.h>

#define N_USERS 100000
#define N_ITEMS 50000
#define N_NODES 150000  // N_USERS + N_ITEMS
#define EMBED   64
#define NNZ     4000000
#define BATCH   4096
#define ROW2    32            // EMBED floats = 32 float2
#define TOTAL2  (N_NODES * ROW2)
#define NQ      (NNZ >> 2)    // 1M edge quads

// ---------------------------------------------------------------------------
// Device-global scratch. Three fp16 layer tables; layer 3 is computed only
// at the 12k batch rows, fused into the final gather (fp32 path).
// ---------------------------------------------------------------------------
__device__ __half g_E0h[N_NODES * EMBED];
__device__ __half g_E1h[N_NODES * EMBED];
__device__ __half g_E2h[N_NODES * EMBED];

__device__ int  g_cnt[N_NODES];    // degree histogram
__device__ int  g_off[N_NODES];    // exclusive offsets
__device__ int  g_rank[NNZ];       // per-edge rank within its row
__device__ int  g_bsum[256];       // per-segment sums (147 used)
__device__ int2 g_edges[NNZ];      // packed (col, a) sorted by row — 32 MB

// ---------------------------------------------------------------------------
// init + hist fused: E0h = fp16(concat(eu, ei));
// rank[e] = cnt[row[e]]++ — launched wide enough that each thread does ONE
// hist quad (4 independent ATOMG in flight, no sequential reuse of the warp).
// ---------------------------------------------------------------------------
__global__ void lgcn_init_hist(const float2* __restrict__ eu,
                               const float2* __restrict__ ei,
                               const int* __restrict__ row) {
    half2* E0h2 = reinterpret_cast<half2*>(g_E0h);
    const int stride = gridDim.x * blockDim.x;
    const int gid = blockIdx.x * blockDim.x + threadIdx.x;
    const int user2 = N_USERS * ROW2;
    for (int i = gid; i < TOTAL2; i += stride) {
        float2 v = (i < user2) ? eu[i] : ei[i - user2];
        E0h2[i] = __float22half2_rn(v);
    }
    if (gid < NQ) {
        const int4* row4 = reinterpret_cast<const int4*>(row);
        int4* rank4 = reinterpret_cast<int4*>(g_rank);
        int4 r = __ldg(row4 + gid);
        int4 k;
        k.x = atomicAdd(&g_cnt[r.x], 1);
        k.y = atomicAdd(&g_cnt[r.y], 1);
        k.z = atomicAdd(&g_cnt[r.z], 1);
        k.w = atomicAdd(&g_cnt[r.w], 1);
        rank4[gid] = k;
    }
}

// ---------------------------------------------------------------------------
// CSR offsets: per-segment scan, then each block derives its own base
// ---------------------------------------------------------------------------
#define SCAN_B 1024
__global__ void k_scan_local() {
    __shared__ int s[SCAN_B];
    const int tid = threadIdx.x;
    const int i = blockIdx.x * SCAN_B + tid;
    int v = (i < N_NODES) ? g_cnt[i] : 0;
    s[tid] = v;
    __syncthreads();
    #pragma unroll
    for (int d = 1; d < SCAN_B; d <<= 1) {
        int t = (tid >= d) ? s[tid - d] : 0;
        __syncthreads();
        s[tid] += t;
        __syncthreads();
    }
    if (i < N_NODES) g_off[i] = s[tid] - v;          // exclusive within segment
    if (tid == SCAN_B - 1) g_bsum[blockIdx.x] = s[tid];
}

__global__ void k_scan_add() {
    __shared__ int base_s;
    const int tid = threadIdx.x;
    if (tid == 0) base_s = 0;
    __syncthreads();
    int partial = 0;
    for (int k = tid; k < blockIdx.x; k += blockDim.x) partial += g_bsum[k];
    #pragma unroll
    for (int d = 16; d; d >>= 1) partial += __shfl_down_sync(0xffffffffu, partial, d);
    if ((tid & 31) == 0 && partial) atomicAdd(&base_s, partial);
    __syncthreads();
    const int i = blockIdx.x * SCAN_B + tid;        // blockDim == SCAN_B
    if (i < N_NODES) g_off[i] += base_s;
}

// ---------------------------------------------------------------------------
// scatter, atomic-free, ONE quad per thread: a thread's entire memory
// burst (4 stream loads + 4 random off loads + 4 random stores) issues
// without sequential-iteration dependencies; MLP comes from warp count.
// ---------------------------------------------------------------------------
__global__ void k_scatter(const int* __restrict__ row,
                          const int* __restrict__ col,
                          const float* __restrict__ a) {
    const int q = blockIdx.x * blockDim.x + threadIdx.x;
    if (q >= NQ) return;
    const int4*   row4  = reinterpret_cast<const int4*>(row);
    const int4*   col4  = reinterpret_cast<const int4*>(col);
    const float4* a4    = reinterpret_cast<const float4*>(a);
    const int4*   rank4 = reinterpret_cast<const int4*>(g_rank);
    int4   r = __ldg(row4 + q);
    int4   k = __ldg(rank4 + q);
    int4   c = __ldg(col4 + q);
    float4 w = __ldg(a4 + q);
    int o0 = __ldg(&g_off[r.x]);
    int o1 = __ldg(&g_off[r.y]);
    int o2 = __ldg(&g_off[r.z]);
    int o3 = __ldg(&g_off[r.w]);
    g_edges[o0 + k.x] = make_int2(c.x, __float_as_int(w.x));
    g_edges[o1 + k.y] = make_int2(c.y, __float_as_int(w.y));
    g_edges[o2 + k.z] = make_int2(c.z, __float_as_int(w.z));
    g_edges[o3 + k.w] = make_int2(c.w, __float_as_int(w.w));
}

// ---------------------------------------------------------------------------
// CSR SpMM, fp16 in/out, fp32 math, software-pipelined, tail-predicated.
// One warp per node; edge-group eg = lane>>3 handles edge base+eg; 8 lanes
// × 16B cover the 128B row. Next edge quad prefetched during the gather;
// out-of-range edge lanes skip the gather entirely (no wasted row-0 loads).
// ---------------------------------------------------------------------------
#define SPMM_T 256
__global__ void lgcn_csr(const uint4* __restrict__ src,
                         uint4* __restrict__ dst) {
    const int warp = (blockIdx.x * SPMM_T + threadIdx.x) >> 5;
    const int lane = threadIdx.x & 31;
    if (warp >= N_NODES) return;
    const int s  = __ldg(&g_off[warp]);
    const int n  = __ldg(&g_cnt[warp]);
    const int eg = lane >> 3;          // 0..3: which edge of the quad
    const int l8 = lane & 7;           // 16B chunk within the 128B row

    float2 s0 = make_float2(0.f, 0.f), s1 = s0, s2 = s0, s3 = s0;
    int2 e_cur = (eg < n) ? __ldg(g_edges + s + eg) : make_int2(0, 0);
    #pragma unroll 2
    for (int base = 0; base < n; base += 4) {
        const int nidx = base + 4 + eg;
        int2 e_next = (nidx < n) ? __ldg(g_edges + s + nidx) : make_int2(0, 0);
        if (base + eg < n) {
            const float av = __int_as_float(e_cur.y);
            uint4 h = __ldg(src + ((size_t)e_cur.x << 3) + l8);
            float2 v0 = __half22float2(*reinterpret_cast<half2*>(&h.x));
            float2 v1 = __half22float2(*reinterpret_cast<half2*>(&h.y));
            float2 v2 = __half22float2(*reinterpret_cast<half2*>(&h.z));
            float2 v3 = __half22float2(*reinterpret_cast<half2*>(&h.w));
            s0.x += av * v0.x; s0.y += av * v0.y;
            s1.x += av * v1.x; s1.y += av * v1.y;
            s2.x += av * v2.x; s2.y += av * v2.y;
            s3.x += av * v3.x; s3.y += av * v3.y;
        }
        e_cur = e_next;
    }
    // combine the 4 edge-groups (lanes with equal l8)
    #pragma unroll
    for (int d = 8; d <= 16; d <<= 1) {
        s0.x += __shfl_xor_sync(0xffffffffu, s0.x, d);
        s0.y += __shfl_xor_sync(0xffffffffu, s0.y, d);
        s1.x += __shfl_xor_sync(0xffffffffu, s1.x, d);
        s1.y += __shfl_xor_sync(0xffffffffu, s1.y, d);
        s2.x += __shfl_xor_sync(0xffffffffu, s2.x, d);
        s2.y += __shfl_xor_sync(0xffffffffu, s2.y, d);
        s3.x += __shfl_xor_sync(0xffffffffu, s3.x, d);
        s3.y += __shfl_xor_sync(0xffffffffu, s3.y, d);
    }
    if (eg == 0) {
        half2 p0 = __floats2half2_rn(s0.x, s0.y);
        half2 p1 = __floats2half2_rn(s1.x, s1.y);
        half2 p2 = __floats2half2_rn(s2.x, s2.y);
        half2 p3 = __floats2half2_rn(s3.x, s3.y);
        uint4 o;
        o.x = *reinterpret_cast<unsigned*>(&p0);
        o.y = *reinterpret_cast<unsigned*>(&p1);
        o.z = *reinterpret_cast<unsigned*>(&p2);
        o.w = *reinterpret_cast<unsigned*>(&p3);
        dst[((size_t)warp << 3) + l8] = o;
    }
}

// ---------------------------------------------------------------------------
// Fused layer-3 + gather (pipelined, predicated like lgcn_csr):
//   e3 = sum_j a[j] * E2[col[j]]   (fp32, never quantized)
//   out[r] = 0.25 * ((E0+E1+E2)[node] + e3)
// ---------------------------------------------------------------------------
__global__ void lgcn_last(const int* __restrict__ bu,
                          const int* __restrict__ bp,
                          const int* __restrict__ bn,
                          float4* __restrict__ out) {
    const int warp = (blockIdx.x * blockDim.x + threadIdx.x) >> 5;
    const int lane = threadIdx.x & 31;
    if (warp >= 3 * BATCH) return;
    const int which = warp / BATCH;
    const int b     = warp - which * BATCH;
    int node;
    if (which == 0)      node = __ldg(bu + b);
    else if (which == 1) node = N_USERS + __ldg(bp + b);
    else                 node = N_USERS + __ldg(bn + b);

    const int s  = __ldg(&g_off[node]);
    const int n  = __ldg(&g_cnt[node]);
    const int eg = lane >> 3;
    const int l8 = lane & 7;

    const uint4* E2 = reinterpret_cast<const uint4*>(g_E2h);
    float2 s0 = make_float2(0.f, 0.f), s1 = s0, s2 = s0, s3 = s0;
    int2 e_cur = (eg < n) ? __ldg(g_edges + s + eg) : make_int2(0, 0);
    for (int base = 0; base < n; base += 4) {
        const int nidx = base + 4 + eg;
        int2 e_next = (nidx < n) ? __ldg(g_edges + s + nidx) : make_int2(0, 0);
        if (base + eg < n) {
            const float av = __int_as_float(e_cur.y);
            uint4 h = __ldg(E2 + ((size_t)e_cur.x << 3) + l8);
            float2 v0 = __half22float2(*reinterpret_cast<half2*>(&h.x));
            float2 v1 = __half22float2(*reinterpret_cast<half2*>(&h.y));
            float2 v2 = __half22float2(*reinterpret_cast<half2*>(&h.z));
            float2 v3 = __half22float2(*reinterpret_cast<half2*>(&h.w));
            s0.x += av * v0.x; s0.y += av * v0.y;
            s1.x += av * v1.x; s1.y += av * v1.y;
            s2.x += av * v2.x; s2.y += av * v2.y;
            s3.x += av * v3.x; s3.y += av * v3.y;
        }
        e_cur = e_next;
    }
    #pragma unroll
    for (int d = 8; d <= 16; d <<= 1) {
        s0.x += __shfl_xor_sync(0xffffffffu, s0.x, d);
        s0.y += __shfl_xor_sync(0xffffffffu, s0.y, d);
        s1.x += __shfl_xor_sync(0xffffffffu, s1.x, d);
        s1.y += __shfl_xor_sync(0xffffffffu, s1.y, d);
        s2.x += __shfl_xor_sync(0xffffffffu, s2.x, d);
        s2.y += __shfl_xor_sync(0xffffffffu, s2.y, d);
        s3.x += __shfl_xor_sync(0xffffffffu, s3.x, d);
        s3.y += __shfl_xor_sync(0xffffffffu, s3.y, d);
    }
    if (eg == 0) {
        const size_t o = ((size_t)node << 3) + l8;
        const uint4* tabs[3] = {
            reinterpret_cast<const uint4*>(g_E0h),
            reinterpret_cast<const uint4*>(g_E1h),
            reinterpret_cast<const uint4*>(g_E2h)
        };
        #pragma unroll
        for (int t = 0; t < 3; t++) {
            uint4 h = __ldg(tabs[t] + o);
            float2 v0 = __half22float2(*reinterpret_cast<half2*>(&h.x));
            float2 v1 = __half22float2(*reinterpret_cast<half2*>(&h.y));
            float2 v2 = __half22float2(*reinterpret_cast<half2*>(&h.z));
            float2 v3 = __half22float2(*reinterpret_cast<half2*>(&h.w));
            s0.x += v0.x; s0.y += v0.y;
            s1.x += v1.x; s1.y += v1.y;
            s2.x += v2.x; s2.y += v2.y;
            s3.x += v3.x; s3.y += v3.y;
        }
        const float sc = 0.25f;   // 1/(N_LAYERS+1)
        float4* orow = out + ((size_t)warp << 4) + l8 * 2;
        orow[0] = make_float4(s0.x * sc, s0.y * sc, s1.x * sc, s1.y * sc);
        orow[1] = make_float4(s2.x * sc, s2.y * sc, s3.x * sc, s3.y * sc);
    }
}

// ---------------------------------------------------------------------------
// launch
// ---------------------------------------------------------------------------
extern "C" void kernel_launch(void* const* d_in, const int* in_sizes, int n_in,
                              void* d_out, int out_size) {
    const int*   batch_user = (const int*)  d_in[0];
    const int*   batch_pos  = (const int*)  d_in[1];
    const int*   batch_neg  = (const int*)  d_in[2];
    const float* embed_user = (const float*)d_in[3];
    const float* embed_item = (const float*)d_in[4];
    const int*   row_idx    = (const int*)  d_in[5];
    const int*   col_idx    = (const int*)  d_in[6];
    const float* a_vals     = (const float*)d_in[7];
    float* out = (float*)d_out;

    uint4 *E0, *E1, *E2;
    void* cntp = nullptr;
    cudaGetSymbolAddress((void**)&E0, g_E0h);
    cudaGetSymbolAddress((void**)&E1, g_E1h);
    cudaGetSymbolAddress((void**)&E2, g_E2h);
    cudaGetSymbolAddress(&cntp, g_cnt);

    const int T = 256;
    const int initBlocks = (NQ + T - 1) / T;                    // 3907: 1 quad/thread
    const int quadBlocks = (NQ + T - 1) / T;                    // 3907
    const int scanBlocks = (N_NODES + SCAN_B - 1) / SCAN_B;     // 147
    const int csrBlocks  = (N_NODES * 32 + SPMM_T - 1) / SPMM_T;
    const int lastBlocks = (3 * BATCH * 32 + T - 1) / T;

    cudaMemsetAsync(cntp, 0, N_NODES * sizeof(int));
    lgcn_init_hist<<<initBlocks, T>>>((const float2*)embed_user,
                                      (const float2*)embed_item, row_idx);

    k_scan_local<<<scanBlocks, SCAN_B>>>();
    k_scan_add<<<scanBlocks, SCAN_B>>>();
    k_scatter<<<quadBlocks, T>>>(row_idx, col_idx, a_vals);

    // layers 1 and 2 over all nodes
    lgcn_csr<<<csrBlocks, SPMM_T>>>(E0, E1);
    lgcn_csr<<<csrBlocks, SPMM_T>>>(E1, E2);

    // fused layer 3 + accumulate + gather over the 12k batch rows only
    lgcn_last<<<lastBlocks, T>>>(batch_user, batch_pos, batch_neg,
                                 (float4*)out);
}

// round 13
// speedup vs baseline: 1.0581x; 1.0581x over previous
#include <cuda_runtime.h>
#include <cuda_fp16.h>

#define N_USERS 100000
#define N_ITEMS 50000
#define N_NODES 150000  // N_USERS + N_ITEMS
#define EMBED   64
#define NNZ     4000000
#define BATCH   4096
#define ROW2    32            // EMBED floats = 32 float2
#define TOTAL2  (N_NODES * ROW2)
#define NQ      (NNZ >> 2)    // 1M edge quads

// ---------------------------------------------------------------------------
// Device-global scratch. Three fp16 layer tables; layer 3 is computed only
// at the 12k batch rows, fused into the final gather (fp32 path).
// ---------------------------------------------------------------------------
__device__ __half g_E0h[N_NODES * EMBED];
__device__ __half g_E1h[N_NODES * EMBED];
__device__ __half g_E2h[N_NODES * EMBED];

__device__ int  g_cnt[N_NODES];    // degree histogram
__device__ int  g_off[N_NODES];    // exclusive offsets
__device__ int  g_rank[NNZ];       // per-edge rank within its row
__device__ int  g_bsum[256];       // per-segment sums (147 used)
__device__ int2 g_edges[NNZ];      // packed (col, a) sorted by row — 32 MB

// ---------------------------------------------------------------------------
// init + hist fused: E0h = fp16(concat(eu, ei));
// rank[e] = cnt[row[e]]++ — one hist quad per thread (4 ATOMG in flight,
// no sequential iteration dependence).
// ---------------------------------------------------------------------------
__global__ void lgcn_init_hist(const float2* __restrict__ eu,
                               const float2* __restrict__ ei,
                               const int* __restrict__ row) {
    half2* E0h2 = reinterpret_cast<half2*>(g_E0h);
    const int stride = gridDim.x * blockDim.x;
    const int gid = blockIdx.x * blockDim.x + threadIdx.x;
    const int user2 = N_USERS * ROW2;
    for (int i = gid; i < TOTAL2; i += stride) {
        float2 v = (i < user2) ? eu[i] : ei[i - user2];
        E0h2[i] = __float22half2_rn(v);
    }
    if (gid < NQ) {
        const int4* row4 = reinterpret_cast<const int4*>(row);
        int4* rank4 = reinterpret_cast<int4*>(g_rank);
        int4 r = __ldg(row4 + gid);
        int4 k;
        k.x = atomicAdd(&g_cnt[r.x], 1);
        k.y = atomicAdd(&g_cnt[r.y], 1);
        k.z = atomicAdd(&g_cnt[r.z], 1);
        k.w = atomicAdd(&g_cnt[r.w], 1);
        rank4[gid] = k;
    }
}

// ---------------------------------------------------------------------------
// CSR offsets: per-segment scan, then each block derives its own base
// ---------------------------------------------------------------------------
#define SCAN_B 1024
__global__ void k_scan_local() {
    __shared__ int s[SCAN_B];
    const int tid = threadIdx.x;
    const int i = blockIdx.x * SCAN_B + tid;
    int v = (i < N_NODES) ? g_cnt[i] : 0;
    s[tid] = v;
    __syncthreads();
    #pragma unroll
    for (int d = 1; d < SCAN_B; d <<= 1) {
        int t = (tid >= d) ? s[tid - d] : 0;
        __syncthreads();
        s[tid] += t;
        __syncthreads();
    }
    if (i < N_NODES) g_off[i] = s[tid] - v;          // exclusive within segment
    if (tid == SCAN_B - 1) g_bsum[blockIdx.x] = s[tid];
}

__global__ void k_scan_add() {
    __shared__ int base_s;
    const int tid = threadIdx.x;
    if (tid == 0) base_s = 0;
    __syncthreads();
    int partial = 0;
    for (int k = tid; k < blockIdx.x; k += blockDim.x) partial += g_bsum[k];
    #pragma unroll
    for (int d = 16; d; d >>= 1) partial += __shfl_down_sync(0xffffffffu, partial, d);
    if ((tid & 31) == 0 && partial) atomicAdd(&base_s, partial);
    __syncthreads();
    const int i = blockIdx.x * SCAN_B + tid;        // blockDim == SCAN_B
    if (i < N_NODES) g_off[i] += base_s;
}

// ---------------------------------------------------------------------------
// scatter, atomic-free, ONE quad per thread (best measured config: 50.4us)
// ---------------------------------------------------------------------------
__global__ void k_scatter(const int* __restrict__ row,
                          const int* __restrict__ col,
                          const float* __restrict__ a) {
    const int q = blockIdx.x * blockDim.x + threadIdx.x;
    if (q >= NQ) return;
    const int4*   row4  = reinterpret_cast<const int4*>(row);
    const int4*   col4  = reinterpret_cast<const int4*>(col);
    const float4* a4    = reinterpret_cast<const float4*>(a);
    const int4*   rank4 = reinterpret_cast<const int4*>(g_rank);
    int4   r = __ldg(row4 + q);
    int4   k = __ldg(rank4 + q);
    int4   c = __ldg(col4 + q);
    float4 w = __ldg(a4 + q);
    int o0 = __ldg(&g_off[r.x]);
    int o1 = __ldg(&g_off[r.y]);
    int o2 = __ldg(&g_off[r.z]);
    int o3 = __ldg(&g_off[r.w]);
    g_edges[o0 + k.x] = make_int2(c.x, __float_as_int(w.x));
    g_edges[o1 + k.y] = make_int2(c.y, __float_as_int(w.y));
    g_edges[o2 + k.z] = make_int2(c.z, __float_as_int(w.z));
    g_edges[o3 + k.w] = make_int2(c.w, __float_as_int(w.w));
}

// ---------------------------------------------------------------------------
// CSR SpMM, fp16 in/out, fp32 math, software-pipelined (R10 body — no tail
// predication: the out-of-range lanes' row-0 broadcast gathers are cheaper
// than a divergent branch in the inner loop).
// ---------------------------------------------------------------------------
#define SPMM_T 256
__global__ void lgcn_csr(const uint4* __restrict__ src,
                         uint4* __restrict__ dst) {
    const int warp = (blockIdx.x * SPMM_T + threadIdx.x) >> 5;
    const int lane = threadIdx.x & 31;
    if (warp >= N_NODES) return;
    const int s  = __ldg(&g_off[warp]);
    const int n  = __ldg(&g_cnt[warp]);
    const int eg = lane >> 3;          // 0..3: which edge of the quad
    const int l8 = lane & 7;           // 16B chunk within the 128B row

    float2 s0 = make_float2(0.f, 0.f), s1 = s0, s2 = s0, s3 = s0;
    int2 e_cur = (eg < n) ? __ldg(g_edges + s + eg) : make_int2(0, 0);
    #pragma unroll 2
    for (int base = 0; base < n; base += 4) {
        // prefetch next quad's edge (independent of this iteration's math)
        const int nidx = base + 4 + eg;
        int2 e_next = (nidx < n) ? __ldg(g_edges + s + nidx) : make_int2(0, 0);
        const float av = __int_as_float(e_cur.y);
        uint4 h = __ldg(src + ((size_t)e_cur.x << 3) + l8);
        float2 v0 = __half22float2(*reinterpret_cast<half2*>(&h.x));
        float2 v1 = __half22float2(*reinterpret_cast<half2*>(&h.y));
        float2 v2 = __half22float2(*reinterpret_cast<half2*>(&h.z));
        float2 v3 = __half22float2(*reinterpret_cast<half2*>(&h.w));
        s0.x += av * v0.x; s0.y += av * v0.y;
        s1.x += av * v1.x; s1.y += av * v1.y;
        s2.x += av * v2.x; s2.y += av * v2.y;
        s3.x += av * v3.x; s3.y += av * v3.y;
        e_cur = e_next;
    }
    // combine the 4 edge-groups (lanes with equal l8)
    #pragma unroll
    for (int d = 8; d <= 16; d <<= 1) {
        s0.x += __shfl_xor_sync(0xffffffffu, s0.x, d);
        s0.y += __shfl_xor_sync(0xffffffffu, s0.y, d);
        s1.x += __shfl_xor_sync(0xffffffffu, s1.x, d);
        s1.y += __shfl_xor_sync(0xffffffffu, s1.y, d);
        s2.x += __shfl_xor_sync(0xffffffffu, s2.x, d);
        s2.y += __shfl_xor_sync(0xffffffffu, s2.y, d);
        s3.x += __shfl_xor_sync(0xffffffffu, s3.x, d);
        s3.y += __shfl_xor_sync(0xffffffffu, s3.y, d);
    }
    if (eg == 0) {
        half2 p0 = __floats2half2_rn(s0.x, s0.y);
        half2 p1 = __floats2half2_rn(s1.x, s1.y);
        half2 p2 = __floats2half2_rn(s2.x, s2.y);
        half2 p3 = __floats2half2_rn(s3.x, s3.y);
        uint4 o;
        o.x = *reinterpret_cast<unsigned*>(&p0);
        o.y = *reinterpret_cast<unsigned*>(&p1);
        o.z = *reinterpret_cast<unsigned*>(&p2);
        o.w = *reinterpret_cast<unsigned*>(&p3);
        dst[((size_t)warp << 3) + l8] = o;
    }
}

// ---------------------------------------------------------------------------
// Fused layer-3 + gather (software-pipelined, unpredicated):
//   e3 = sum_j a[j] * E2[col[j]]   (fp32, never quantized)
//   out[r] = 0.25 * ((E0+E1+E2)[node] + e3)
// ---------------------------------------------------------------------------
__global__ void lgcn_last(const int* __restrict__ bu,
                          const int* __restrict__ bp,
                          const int* __restrict__ bn,
                          float4* __restrict__ out) {
    const int warp = (blockIdx.x * blockDim.x + threadIdx.x) >> 5;
    const int lane = threadIdx.x & 31;
    if (warp >= 3 * BATCH) return;
    const int which = warp / BATCH;
    const int b     = warp - which * BATCH;
    int node;
    if (which == 0)      node = __ldg(bu + b);
    else if (which == 1) node = N_USERS + __ldg(bp + b);
    else                 node = N_USERS + __ldg(bn + b);

    const int s  = __ldg(&g_off[node]);
    const int n  = __ldg(&g_cnt[node]);
    const int eg = lane >> 3;
    const int l8 = lane & 7;

    const uint4* E2 = reinterpret_cast<const uint4*>(g_E2h);
    float2 s0 = make_float2(0.f, 0.f), s1 = s0, s2 = s0, s3 = s0;
    int2 e_cur = (eg < n) ? __ldg(g_edges + s + eg) : make_int2(0, 0);
    for (int base = 0; base < n; base += 4) {
        const int nidx = base + 4 + eg;
        int2 e_next = (nidx < n) ? __ldg(g_edges + s + nidx) : make_int2(0, 0);
        const float av = __int_as_float(e_cur.y);
        uint4 h = __ldg(E2 + ((size_t)e_cur.x << 3) + l8);
        float2 v0 = __half22float2(*reinterpret_cast<half2*>(&h.x));
        float2 v1 = __half22float2(*reinterpret_cast<half2*>(&h.y));
        float2 v2 = __half22float2(*reinterpret_cast<half2*>(&h.z));
        float2 v3 = __half22float2(*reinterpret_cast<half2*>(&h.w));
        s0.x += av * v0.x; s0.y += av * v0.y;
        s1.x += av * v1.x; s1.y += av * v1.y;
        s2.x += av * v2.x; s2.y += av * v2.y;
        s3.x += av * v3.x; s3.y += av * v3.y;
        e_cur = e_next;
    }
    #pragma unroll
    for (int d = 8; d <= 16; d <<= 1) {
        s0.x += __shfl_xor_sync(0xffffffffu, s0.x, d);
        s0.y += __shfl_xor_sync(0xffffffffu, s0.y, d);
        s1.x += __shfl_xor_sync(0xffffffffu, s1.x, d);
        s1.y += __shfl_xor_sync(0xffffffffu, s1.y, d);
        s2.x += __shfl_xor_sync(0xffffffffu, s2.x, d);
        s2.y += __shfl_xor_sync(0xffffffffu, s2.y, d);
        s3.x += __shfl_xor_sync(0xffffffffu, s3.x, d);
        s3.y += __shfl_xor_sync(0xffffffffu, s3.y, d);
    }
    if (eg == 0) {
        const size_t o = ((size_t)node << 3) + l8;
        const uint4* tabs[3] = {
            reinterpret_cast<const uint4*>(g_E0h),
            reinterpret_cast<const uint4*>(g_E1h),
            reinterpret_cast<const uint4*>(g_E2h)
        };
        #pragma unroll
        for (int t = 0; t < 3; t++) {
            uint4 h = __ldg(tabs[t] + o);
            float2 v0 = __half22float2(*reinterpret_cast<half2*>(&h.x));
            float2 v1 = __half22float2(*reinterpret_cast<half2*>(&h.y));
            float2 v2 = __half22float2(*reinterpret_cast<half2*>(&h.z));
            float2 v3 = __half22float2(*reinterpret_cast<half2*>(&h.w));
            s0.x += v0.x; s0.y += v0.y;
            s1.x += v1.x; s1.y += v1.y;
            s2.x += v2.x; s2.y += v2.y;
            s3.x += v3.x; s3.y += v3.y;
        }
        const float sc = 0.25f;   // 1/(N_LAYERS+1)
        float4* orow = out + ((size_t)warp << 4) + l8 * 2;
        orow[0] = make_float4(s0.x * sc, s0.y * sc, s1.x * sc, s1.y * sc);
        orow[1] = make_float4(s2.x * sc, s2.y * sc, s3.x * sc, s3.y * sc);
    }
}

// ---------------------------------------------------------------------------
// launch
// ---------------------------------------------------------------------------
extern "C" void kernel_launch(void* const* d_in, const int* in_sizes, int n_in,
                              void* d_out, int out_size) {
    const int*   batch_user = (const int*)  d_in[0];
    const int*   batch_pos  = (const int*)  d_in[1];
    const int*   batch_neg  = (const int*)  d_in[2];
    const float* embed_user = (const float*)d_in[3];
    const float* embed_item = (const float*)d_in[4];
    const int*   row_idx    = (const int*)  d_in[5];
    const int*   col_idx    = (const int*)  d_in[6];
    const float* a_vals     = (const float*)d_in[7];
    float* out = (float*)d_out;

    uint4 *E0, *E1, *E2;
    void* cntp = nullptr;
    cudaGetSymbolAddress((void**)&E0, g_E0h);
    cudaGetSymbolAddress((void**)&E1, g_E1h);
    cudaGetSymbolAddress((void**)&E2, g_E2h);
    cudaGetSymbolAddress(&cntp, g_cnt);

    const int T = 256;
    const int initBlocks = (NQ + T - 1) / T;                    // 3907: 1 quad/thread
    const int quadBlocks = (NQ + T - 1) / T;                    // 3907
    const int scanBlocks = (N_NODES + SCAN_B - 1) / SCAN_B;     // 147
    const int csrBlocks  = (N_NODES * 32 + SPMM_T - 1) / SPMM_T;
    const int lastBlocks = (3 * BATCH * 32 + T - 1) / T;

    cudaMemsetAsync(cntp, 0, N_NODES * sizeof(int));
    lgcn_init_hist<<<initBlocks, T>>>((const float2*)embed_user,
                                      (const float2*)embed_item, row_idx);

    k_scan_local<<<scanBlocks, SCAN_B>>>();
    k_scan_add<<<scanBlocks, SCAN_B>>>();
    k_scatter<<<quadBlocks, T>>>(row_idx, col_idx, a_vals);

    // layers 1 and 2 over all nodes
    lgcn_csr<<<csrBlocks, SPMM_T>>>(E0, E1);
    lgcn_csr<<<csrBlocks, SPMM_T>>>(E1, E2);

    // fused layer 3 + accumulate + gather over the 12k batch rows only
    lgcn_last<<<lastBlocks, T>>>(batch_user, batch_pos, batch_neg,
                                 (float4*)out);
}

// round 14
// speedup vs baseline: 1.1992x; 1.1334x over previous
#include <cuda_runtime.h>
#include <cuda_fp16.h>

#define N_USERS 100000
#define N_ITEMS 50000
#define N_NODES 150000  // N_USERS + N_ITEMS
#define EMBED   64
#define NNZ     4000000
#define BATCH   4096
#define ROW2    32            // EMBED floats = 32 float2
#define TOTAL2  (N_NODES * ROW2)
#define NQ      (NNZ >> 2)    // 1M edge quads

// Edge packing: bits[0:18) = col (N_NODES < 2^18), bits[18:32) = a as
// 14-bit fixed point in [0,1]. |quant err| <= 3.05e-5 absolute.
#define COL_MASK 0x3FFFFu
#define A_SCALE  16383.0f
#define A_INV    (1.0f / 16383.0f)

// ---------------------------------------------------------------------------
// Device-global scratch. Three fp16 layer tables; layer 3 is computed only
// at the 12k batch rows, fused into the final gather (fp32 path).
// ---------------------------------------------------------------------------
__device__ __half g_E0h[N_NODES * EMBED];
__device__ __half g_E1h[N_NODES * EMBED];
__device__ __half g_E2h[N_NODES * EMBED];

__device__ int           g_cnt[N_NODES];   // degree histogram
__device__ int           g_off[N_NODES];   // exclusive offsets
__device__ unsigned char g_rank[NNZ];      // per-edge rank (max degree ~52)
__device__ int           g_bsum[256];      // per-segment sums (147 used)
__device__ unsigned      g_edges[NNZ];     // packed (col|a14) sorted by row — 16 MB

// ---------------------------------------------------------------------------
// init + hist fused: E0h = fp16(concat(eu, ei));
// rank[e] = cnt[row[e]]++ — one hist quad per thread, rank stored as uchar4.
// ---------------------------------------------------------------------------
__global__ void lgcn_init_hist(const float2* __restrict__ eu,
                               const float2* __restrict__ ei,
                               const int* __restrict__ row) {
    half2* E0h2 = reinterpret_cast<half2*>(g_E0h);
    const int stride = gridDim.x * blockDim.x;
    const int gid = blockIdx.x * blockDim.x + threadIdx.x;
    const int user2 = N_USERS * ROW2;
    for (int i = gid; i < TOTAL2; i += stride) {
        float2 v = (i < user2) ? eu[i] : ei[i - user2];
        E0h2[i] = __float22half2_rn(v);
    }
    if (gid < NQ) {
        const int4* row4 = reinterpret_cast<const int4*>(row);
        int4 r = __ldg(row4 + gid);
        uchar4 k;
        k.x = (unsigned char)atomicAdd(&g_cnt[r.x], 1);
        k.y = (unsigned char)atomicAdd(&g_cnt[r.y], 1);
        k.z = (unsigned char)atomicAdd(&g_cnt[r.z], 1);
        k.w = (unsigned char)atomicAdd(&g_cnt[r.w], 1);
        reinterpret_cast<uchar4*>(g_rank)[gid] = k;
    }
}

// ---------------------------------------------------------------------------
// CSR offsets: per-segment scan, then each block derives its own base
// ---------------------------------------------------------------------------
#define SCAN_B 1024
__global__ void k_scan_local() {
    __shared__ int s[SCAN_B];
    const int tid = threadIdx.x;
    const int i = blockIdx.x * SCAN_B + tid;
    int v = (i < N_NODES) ? g_cnt[i] : 0;
    s[tid] = v;
    __syncthreads();
    #pragma unroll
    for (int d = 1; d < SCAN_B; d <<= 1) {
        int t = (tid >= d) ? s[tid - d] : 0;
        __syncthreads();
        s[tid] += t;
        __syncthreads();
    }
    if (i < N_NODES) g_off[i] = s[tid] - v;          // exclusive within segment
    if (tid == SCAN_B - 1) g_bsum[blockIdx.x] = s[tid];
}

__global__ void k_scan_add() {
    __shared__ int base_s;
    const int tid = threadIdx.x;
    if (tid == 0) base_s = 0;
    __syncthreads();
    int partial = 0;
    for (int k = tid; k < blockIdx.x; k += blockDim.x) partial += g_bsum[k];
    #pragma unroll
    for (int d = 16; d; d >>= 1) partial += __shfl_down_sync(0xffffffffu, partial, d);
    if ((tid & 31) == 0 && partial) atomicAdd(&base_s, partial);
    __syncthreads();
    const int i = blockIdx.x * SCAN_B + tid;        // blockDim == SCAN_B
    if (i < N_NODES) g_off[i] += base_s;
}

// ---------------------------------------------------------------------------
// scatter, atomic-free, ONE quad per thread, 4B packed edge payload:
// random-store traffic halves vs int2 edges.
// ---------------------------------------------------------------------------
__global__ void k_scatter(const int* __restrict__ row,
                          const int* __restrict__ col,
                          const float* __restrict__ a) {
    const int q = blockIdx.x * blockDim.x + threadIdx.x;
    if (q >= NQ) return;
    const int4*   row4  = reinterpret_cast<const int4*>(row);
    const int4*   col4  = reinterpret_cast<const int4*>(col);
    const float4* a4    = reinterpret_cast<const float4*>(a);
    const uchar4* rank4 = reinterpret_cast<const uchar4*>(g_rank);
    int4   r = __ldg(row4 + q);
    uchar4 k = __ldg(rank4 + q);
    int4   c = __ldg(col4 + q);
    float4 w = __ldg(a4 + q);
    int o0 = __ldg(&g_off[r.x]);
    int o1 = __ldg(&g_off[r.y]);
    int o2 = __ldg(&g_off[r.z]);
    int o3 = __ldg(&g_off[r.w]);
    g_edges[o0 + k.x] = (unsigned)c.x | (__float2uint_rn(w.x * A_SCALE) << 18);
    g_edges[o1 + k.y] = (unsigned)c.y | (__float2uint_rn(w.y * A_SCALE) << 18);
    g_edges[o2 + k.z] = (unsigned)c.z | (__float2uint_rn(w.z * A_SCALE) << 18);
    g_edges[o3 + k.w] = (unsigned)c.w | (__float2uint_rn(w.w * A_SCALE) << 18);
}

// ---------------------------------------------------------------------------
// CSR SpMM, fp16 in/out, fp32 math, software-pipelined, 4B packed edges.
// One warp per node; edge-group eg = lane>>3 handles edge base+eg; 8 lanes
// × 16B cover the 128B row. Next edge quad prefetched during the gather.
// ---------------------------------------------------------------------------
#define SPMM_T 256
__global__ void lgcn_csr(const uint4* __restrict__ src,
                         uint4* __restrict__ dst) {
    const int warp = (blockIdx.x * SPMM_T + threadIdx.x) >> 5;
    const int lane = threadIdx.x & 31;
    if (warp >= N_NODES) return;
    const int s  = __ldg(&g_off[warp]);
    const int n  = __ldg(&g_cnt[warp]);
    const int eg = lane >> 3;          // 0..3: which edge of the quad
    const int l8 = lane & 7;           // 16B chunk within the 128B row

    float2 s0 = make_float2(0.f, 0.f), s1 = s0, s2 = s0, s3 = s0;
    unsigned e_cur = (eg < n) ? __ldg(g_edges + s + eg) : 0u;
    #pragma unroll 2
    for (int base = 0; base < n; base += 4) {
        // prefetch next quad's edge (independent of this iteration's math)
        const int nidx = base + 4 + eg;
        unsigned e_next = (nidx < n) ? __ldg(g_edges + s + nidx) : 0u;
        const float av = (float)(e_cur >> 18) * A_INV;
        uint4 h = __ldg(src + ((size_t)(e_cur & COL_MASK) << 3) + l8);
        float2 v0 = __half22float2(*reinterpret_cast<half2*>(&h.x));
        float2 v1 = __half22float2(*reinterpret_cast<half2*>(&h.y));
        float2 v2 = __half22float2(*reinterpret_cast<half2*>(&h.z));
        float2 v3 = __half22float2(*reinterpret_cast<half2*>(&h.w));
        s0.x += av * v0.x; s0.y += av * v0.y;
        s1.x += av * v1.x; s1.y += av * v1.y;
        s2.x += av * v2.x; s2.y += av * v2.y;
        s3.x += av * v3.x; s3.y += av * v3.y;
        e_cur = e_next;
    }
    // combine the 4 edge-groups (lanes with equal l8)
    #pragma unroll
    for (int d = 8; d <= 16; d <<= 1) {
        s0.x += __shfl_xor_sync(0xffffffffu, s0.x, d);
        s0.y += __shfl_xor_sync(0xffffffffu, s0.y, d);
        s1.x += __shfl_xor_sync(0xffffffffu, s1.x, d);
        s1.y += __shfl_xor_sync(0xffffffffu, s1.y, d);
        s2.x += __shfl_xor_sync(0xffffffffu, s2.x, d);
        s2.y += __shfl_xor_sync(0xffffffffu, s2.y, d);
        s3.x += __shfl_xor_sync(0xffffffffu, s3.x, d);
        s3.y += __shfl_xor_sync(0xffffffffu, s3.y, d);
    }
    if (eg == 0) {
        half2 p0 = __floats2half2_rn(s0.x, s0.y);
        half2 p1 = __floats2half2_rn(s1.x, s1.y);
        half2 p2 = __floats2half2_rn(s2.x, s2.y);
        half2 p3 = __floats2half2_rn(s3.x, s3.y);
        uint4 o;
        o.x = *reinterpret_cast<unsigned*>(&p0);
        o.y = *reinterpret_cast<unsigned*>(&p1);
        o.z = *reinterpret_cast<unsigned*>(&p2);
        o.w = *reinterpret_cast<unsigned*>(&p3);
        dst[((size_t)warp << 3) + l8] = o;
    }
}

// ---------------------------------------------------------------------------
// Fused layer-3 + gather (software-pipelined, packed edges):
//   e3 = sum_j a[j] * E2[col[j]]   (fp32, never quantized to fp16)
//   out[r] = 0.25 * ((E0+E1+E2)[node] + e3)
// ---------------------------------------------------------------------------
__global__ void lgcn_last(const int* __restrict__ bu,
                          const int* __restrict__ bp,
                          const int* __restrict__ bn,
                          float4* __restrict__ out) {
    const int warp = (blockIdx.x * blockDim.x + threadIdx.x) >> 5;
    const int lane = threadIdx.x & 31;
    if (warp >= 3 * BATCH) return;
    const int which = warp / BATCH;
    const int b     = warp - which * BATCH;
    int node;
    if (which == 0)      node = __ldg(bu + b);
    else if (which == 1) node = N_USERS + __ldg(bp + b);
    else                 node = N_USERS + __ldg(bn + b);

    const int s  = __ldg(&g_off[node]);
    const int n  = __ldg(&g_cnt[node]);
    const int eg = lane >> 3;
    const int l8 = lane & 7;

    const uint4* E2 = reinterpret_cast<const uint4*>(g_E2h);
    float2 s0 = make_float2(0.f, 0.f), s1 = s0, s2 = s0, s3 = s0;
    unsigned e_cur = (eg < n) ? __ldg(g_edges + s + eg) : 0u;
    for (int base = 0; base < n; base += 4) {
        const int nidx = base + 4 + eg;
        unsigned e_next = (nidx < n) ? __ldg(g_edges + s + nidx) : 0u;
        const float av = (float)(e_cur >> 18) * A_INV;
        uint4 h = __ldg(E2 + ((size_t)(e_cur & COL_MASK) << 3) + l8);
        float2 v0 = __half22float2(*reinterpret_cast<half2*>(&h.x));
        float2 v1 = __half22float2(*reinterpret_cast<half2*>(&h.y));
        float2 v2 = __half22float2(*reinterpret_cast<half2*>(&h.z));
        float2 v3 = __half22float2(*reinterpret_cast<half2*>(&h.w));
        s0.x += av * v0.x; s0.y += av * v0.y;
        s1.x += av * v1.x; s1.y += av * v1.y;
        s2.x += av * v2.x; s2.y += av * v2.y;
        s3.x += av * v3.x; s3.y += av * v3.y;
        e_cur = e_next;
    }
    #pragma unroll
    for (int d = 8; d <= 16; d <<= 1) {
        s0.x += __shfl_xor_sync(0xffffffffu, s0.x, d);
        s0.y += __shfl_xor_sync(0xffffffffu, s0.y, d);
        s1.x += __shfl_xor_sync(0xffffffffu, s1.x, d);
        s1.y += __shfl_xor_sync(0xffffffffu, s1.y, d);
        s2.x += __shfl_xor_sync(0xffffffffu, s2.x, d);
        s2.y += __shfl_xor_sync(0xffffffffu, s2.y, d);
        s3.x += __shfl_xor_sync(0xffffffffu, s3.x, d);
        s3.y += __shfl_xor_sync(0xffffffffu, s3.y, d);
    }
    if (eg == 0) {
        const size_t o = ((size_t)node << 3) + l8;
        const uint4* tabs[3] = {
            reinterpret_cast<const uint4*>(g_E0h),
            reinterpret_cast<const uint4*>(g_E1h),
            reinterpret_cast<const uint4*>(g_E2h)
        };
        #pragma unroll
        for (int t = 0; t < 3; t++) {
            uint4 h = __ldg(tabs[t] + o);
            float2 v0 = __half22float2(*reinterpret_cast<half2*>(&h.x));
            float2 v1 = __half22float2(*reinterpret_cast<half2*>(&h.y));
            float2 v2 = __half22float2(*reinterpret_cast<half2*>(&h.z));
            float2 v3 = __half22float2(*reinterpret_cast<half2*>(&h.w));
            s0.x += v0.x; s0.y += v0.y;
            s1.x += v1.x; s1.y += v1.y;
            s2.x += v2.x; s2.y += v2.y;
            s3.x += v3.x; s3.y += v3.y;
        }
        const float sc = 0.25f;   // 1/(N_LAYERS+1)
        float4* orow = out + ((size_t)warp << 4) + l8 * 2;
        orow[0] = make_float4(s0.x * sc, s0.y * sc, s1.x * sc, s1.y * sc);
        orow[1] = make_float4(s2.x * sc, s2.y * sc, s3.x * sc, s3.y * sc);
    }
}

// ---------------------------------------------------------------------------
// launch
// ---------------------------------------------------------------------------
extern "C" void kernel_launch(void* const* d_in, const int* in_sizes, int n_in,
                              void* d_out, int out_size) {
    const int*   batch_user = (const int*)  d_in[0];
    const int*   batch_pos  = (const int*)  d_in[1];
    const int*   batch_neg  = (const int*)  d_in[2];
    const float* embed_user = (const float*)d_in[3];
    const float* embed_item = (const float*)d_in[4];
    const int*   row_idx    = (const int*)  d_in[5];
    const int*   col_idx    = (const int*)  d_in[6];
    const float* a_vals     = (const float*)d_in[7];
    float* out = (float*)d_out;

    uint4 *E0, *E1, *E2;
    void* cntp = nullptr;
    cudaGetSymbolAddress((void**)&E0, g_E0h);
    cudaGetSymbolAddress((void**)&E1, g_E1h);
    cudaGetSymbolAddress((void**)&E2, g_E2h);
    cudaGetSymbolAddress(&cntp, g_cnt);

    const int T = 256;
    const int initBlocks = (NQ + T - 1) / T;                    // 3907: 1 quad/thread
    const int quadBlocks = (NQ + T - 1) / T;                    // 3907
    const int scanBlocks = (N_NODES + SCAN_B - 1) / SCAN_B;     // 147
    const int csrBlocks  = (N_NODES * 32 + SPMM_T - 1) / SPMM_T;
    const int lastBlocks = (3 * BATCH * 32 + T - 1) / T;

    cudaMemsetAsync(cntp, 0, N_NODES * sizeof(int));
    lgcn_init_hist<<<initBlocks, T>>>((const float2*)embed_user,
                                      (const float2*)embed_item, row_idx);

    k_scan_local<<<scanBlocks, SCAN_B>>>();
    k_scan_add<<<scanBlocks, SCAN_B>>>();
    k_scatter<<<quadBlocks, T>>>(row_idx, col_idx, a_vals);

    // layers 1 and 2 over all nodes
    lgcn_csr<<<csrBlocks, SPMM_T>>>(E0, E1);
    lgcn_csr<<<csrBlocks, SPMM_T>>>(E1, E2);

    // fused layer 3 + accumulate + gather over the 12k batch rows only
    lgcn_last<<<lastBlocks, T>>>(batch_user, batch_pos, batch_neg,
                                 (float4*)out);
}

// round 15
// speedup vs baseline: 1.3869x; 1.1565x over previous
#include <cuda_runtime.h>
#include <cuda_fp16.h>

#define N_USERS 100000
#define N_ITEMS 50000
#define N_NODES 150000  // N_USERS + N_ITEMS
#define EMBED   64
#define NNZ     4000000
#define BATCH   4096
#define ROW2    32            // EMBED floats = 32 float2
#define TOTAL2  (N_NODES * ROW2)
#define NQ      (NNZ >> 2)    // 1M edge quads

// Edge packing: bits[0:18) = col (N_NODES < 2^18), bits[18:32) = a as
// 14-bit fixed point in [0,1]. |quant err| <= 3.05e-5 absolute.
#define COL_MASK 0x3FFFFu
#define A_SCALE  16383.0f
#define A_INV    (1.0f / 16383.0f)

// Padded bucket capacity: degrees ~ Poisson(26.7), max over 150k nodes ~52.
#define CAP_LG 6              // 64 slots * 4B = 256B per node bucket
#define CAP    (1 << CAP_LG)

// ---------------------------------------------------------------------------
// Device-global scratch. Three fp16 layer tables; layer 3 is computed only
// at the 12k batch rows, fused into the final gather (fp32 path).
// Edges live in padded 4B buckets (38.4 MB) — slot index comes straight
// from the histogram atomic, so hist+scatter is ONE pass and no scan/rank
// machinery exists at all.
// ---------------------------------------------------------------------------
__device__ __half g_E0h[N_NODES * EMBED];
__device__ __half g_E1h[N_NODES * EMBED];
__device__ __half g_E2h[N_NODES * EMBED];

__device__ int      g_cnt[N_NODES];            // degree / slot cursor
__device__ unsigned g_ebuck[N_NODES * CAP];    // packed (col|a14) buckets

// ---------------------------------------------------------------------------
// Fused init + build: E0h = fp16(concat(eu, ei));
// per edge: k = cnt[r]++ ; bucket[r*CAP + k] = pack(col, a).
// One edge quad per thread: 4 independent ATOMG+STG chains in flight.
// ---------------------------------------------------------------------------
__global__ void lgcn_init_build(const float2* __restrict__ eu,
                                const float2* __restrict__ ei,
                                const int* __restrict__ row,
                                const int* __restrict__ col,
                                const float* __restrict__ a) {
    half2* E0h2 = reinterpret_cast<half2*>(g_E0h);
    const int stride = gridDim.x * blockDim.x;
    const int gid = blockIdx.x * blockDim.x + threadIdx.x;
    const int user2 = N_USERS * ROW2;
    for (int i = gid; i < TOTAL2; i += stride) {
        float2 v = (i < user2) ? eu[i] : ei[i - user2];
        E0h2[i] = __float22half2_rn(v);
    }
    if (gid < NQ) {
        const int4*   row4 = reinterpret_cast<const int4*>(row);
        const int4*   col4 = reinterpret_cast<const int4*>(col);
        const float4* a4   = reinterpret_cast<const float4*>(a);
        int4   r = __ldg(row4 + gid);
        int4   c = __ldg(col4 + gid);
        float4 w = __ldg(a4 + gid);
        unsigned p0 = (unsigned)c.x | (__float2uint_rn(w.x * A_SCALE) << 18);
        unsigned p1 = (unsigned)c.y | (__float2uint_rn(w.y * A_SCALE) << 18);
        unsigned p2 = (unsigned)c.z | (__float2uint_rn(w.z * A_SCALE) << 18);
        unsigned p3 = (unsigned)c.w | (__float2uint_rn(w.w * A_SCALE) << 18);
        int k0 = atomicAdd(&g_cnt[r.x], 1);
        int k1 = atomicAdd(&g_cnt[r.y], 1);
        int k2 = atomicAdd(&g_cnt[r.z], 1);
        int k3 = atomicAdd(&g_cnt[r.w], 1);
        g_ebuck[((size_t)r.x << CAP_LG) + k0] = p0;
        g_ebuck[((size_t)r.y << CAP_LG) + k1] = p1;
        g_ebuck[((size_t)r.z << CAP_LG) + k2] = p2;
        g_ebuck[((size_t)r.w << CAP_LG) + k3] = p3;
    }
}

// ---------------------------------------------------------------------------
// Bucket SpMM, fp16 in/out, fp32 math, software-pipelined, 4B packed edges.
// One warp per node; edge-group eg = lane>>3 handles edge base+eg; 8 lanes
// × 16B cover the 128B row. Next edge quad prefetched during the gather.
// Bucket base = node << CAP_LG (no offset array).
// ---------------------------------------------------------------------------
#define SPMM_T 256
__global__ void lgcn_csr(const uint4* __restrict__ src,
                         uint4* __restrict__ dst) {
    const int warp = (blockIdx.x * SPMM_T + threadIdx.x) >> 5;
    const int lane = threadIdx.x & 31;
    if (warp >= N_NODES) return;
    const unsigned* eb = g_ebuck + ((size_t)warp << CAP_LG);
    const int n  = __ldg(&g_cnt[warp]);
    const int eg = lane >> 3;          // 0..3: which edge of the quad
    const int l8 = lane & 7;           // 16B chunk within the 128B row

    float2 s0 = make_float2(0.f, 0.f), s1 = s0, s2 = s0, s3 = s0;
    unsigned e_cur = (eg < n) ? __ldg(eb + eg) : 0u;
    #pragma unroll 2
    for (int base = 0; base < n; base += 4) {
        // prefetch next quad's edge (independent of this iteration's math)
        const int nidx = base + 4 + eg;
        unsigned e_next = (nidx < n) ? __ldg(eb + nidx) : 0u;
        const float av = (float)(e_cur >> 18) * A_INV;
        uint4 h = __ldg(src + ((size_t)(e_cur & COL_MASK) << 3) + l8);
        float2 v0 = __half22float2(*reinterpret_cast<half2*>(&h.x));
        float2 v1 = __half22float2(*reinterpret_cast<half2*>(&h.y));
        float2 v2 = __half22float2(*reinterpret_cast<half2*>(&h.z));
        float2 v3 = __half22float2(*reinterpret_cast<half2*>(&h.w));
        s0.x += av * v0.x; s0.y += av * v0.y;
        s1.x += av * v1.x; s1.y += av * v1.y;
        s2.x += av * v2.x; s2.y += av * v2.y;
        s3.x += av * v3.x; s3.y += av * v3.y;
        e_cur = e_next;
    }
    // combine the 4 edge-groups (lanes with equal l8)
    #pragma unroll
    for (int d = 8; d <= 16; d <<= 1) {
        s0.x += __shfl_xor_sync(0xffffffffu, s0.x, d);
        s0.y += __shfl_xor_sync(0xffffffffu, s0.y, d);
        s1.x += __shfl_xor_sync(0xffffffffu, s1.x, d);
        s1.y += __shfl_xor_sync(0xffffffffu, s1.y, d);
        s2.x += __shfl_xor_sync(0xffffffffu, s2.x, d);
        s2.y += __shfl_xor_sync(0xffffffffu, s2.y, d);
        s3.x += __shfl_xor_sync(0xffffffffu, s3.x, d);
        s3.y += __shfl_xor_sync(0xffffffffu, s3.y, d);
    }
    if (eg == 0) {
        half2 p0 = __floats2half2_rn(s0.x, s0.y);
        half2 p1 = __floats2half2_rn(s1.x, s1.y);
        half2 p2 = __floats2half2_rn(s2.x, s2.y);
        half2 p3 = __floats2half2_rn(s3.x, s3.y);
        uint4 o;
        o.x = *reinterpret_cast<unsigned*>(&p0);
        o.y = *reinterpret_cast<unsigned*>(&p1);
        o.z = *reinterpret_cast<unsigned*>(&p2);
        o.w = *reinterpret_cast<unsigned*>(&p3);
        dst[((size_t)warp << 3) + l8] = o;
    }
}

// ---------------------------------------------------------------------------
// Fused layer-3 + gather (software-pipelined, packed bucket edges):
//   e3 = sum_j a[j] * E2[col[j]]   (fp32, never quantized to fp16)
//   out[r] = 0.25 * ((E0+E1+E2)[node] + e3)
// ---------------------------------------------------------------------------
__global__ void lgcn_last(const int* __restrict__ bu,
                          const int* __restrict__ bp,
                          const int* __restrict__ bn,
                          float4* __restrict__ out) {
    const int warp = (blockIdx.x * blockDim.x + threadIdx.x) >> 5;
    const int lane = threadIdx.x & 31;
    if (warp >= 3 * BATCH) return;
    const int which = warp / BATCH;
    const int b     = warp - which * BATCH;
    int node;
    if (which == 0)      node = __ldg(bu + b);
    else if (which == 1) node = N_USERS + __ldg(bp + b);
    else                 node = N_USERS + __ldg(bn + b);

    const unsigned* eb = g_ebuck + ((size_t)node << CAP_LG);
    const int n  = __ldg(&g_cnt[node]);
    const int eg = lane >> 3;
    const int l8 = lane & 7;

    const uint4* E2 = reinterpret_cast<const uint4*>(g_E2h);
    float2 s0 = make_float2(0.f, 0.f), s1 = s0, s2 = s0, s3 = s0;
    unsigned e_cur = (eg < n) ? __ldg(eb + eg) : 0u;
    for (int base = 0; base < n; base += 4) {
        const int nidx = base + 4 + eg;
        unsigned e_next = (nidx < n) ? __ldg(eb + nidx) : 0u;
        const float av = (float)(e_cur >> 18) * A_INV;
        uint4 h = __ldg(E2 + ((size_t)(e_cur & COL_MASK) << 3) + l8);
        float2 v0 = __half22float2(*reinterpret_cast<half2*>(&h.x));
        float2 v1 = __half22float2(*reinterpret_cast<half2*>(&h.y));
        float2 v2 = __half22float2(*reinterpret_cast<half2*>(&h.z));
        float2 v3 = __half22float2(*reinterpret_cast<half2*>(&h.w));
        s0.x += av * v0.x; s0.y += av * v0.y;
        s1.x += av * v1.x; s1.y += av * v1.y;
        s2.x += av * v2.x; s2.y += av * v2.y;
        s3.x += av * v3.x; s3.y += av * v3.y;
        e_cur = e_next;
    }
    #pragma unroll
    for (int d = 8; d <= 16; d <<= 1) {
        s0.x += __shfl_xor_sync(0xffffffffu, s0.x, d);
        s0.y += __shfl_xor_sync(0xffffffffu, s0.y, d);
        s1.x += __shfl_xor_sync(0xffffffffu, s1.x, d);
        s1.y += __shfl_xor_sync(0xffffffffu, s1.y, d);
        s2.x += __shfl_xor_sync(0xffffffffu, s2.x, d);
        s2.y += __shfl_xor_sync(0xffffffffu, s2.y, d);
        s3.x += __shfl_xor_sync(0xffffffffu, s3.x, d);
        s3.y += __shfl_xor_sync(0xffffffffu, s3.y, d);
    }
    if (eg == 0) {
        const size_t o = ((size_t)node << 3) + l8;
        const uint4* tabs[3] = {
            reinterpret_cast<const uint4*>(g_E0h),
            reinterpret_cast<const uint4*>(g_E1h),
            reinterpret_cast<const uint4*>(g_E2h)
        };
        #pragma unroll
        for (int t = 0; t < 3; t++) {
            uint4 h = __ldg(tabs[t] + o);
            float2 v0 = __half22float2(*reinterpret_cast<half2*>(&h.x));
            float2 v1 = __half22float2(*reinterpret_cast<half2*>(&h.y));
            float2 v2 = __half22float2(*reinterpret_cast<half2*>(&h.z));
            float2 v3 = __half22float2(*reinterpret_cast<half2*>(&h.w));
            s0.x += v0.x; s0.y += v0.y;
            s1.x += v1.x; s1.y += v1.y;
            s2.x += v2.x; s2.y += v2.y;
            s3.x += v3.x; s3.y += v3.y;
        }
        const float sc = 0.25f;   // 1/(N_LAYERS+1)
        float4* orow = out + ((size_t)warp << 4) + l8 * 2;
        orow[0] = make_float4(s0.x * sc, s0.y * sc, s1.x * sc, s1.y * sc);
        orow[1] = make_float4(s2.x * sc, s2.y * sc, s3.x * sc, s3.y * sc);
    }
}

// ---------------------------------------------------------------------------
// launch
// ---------------------------------------------------------------------------
extern "C" void kernel_launch(void* const* d_in, const int* in_sizes, int n_in,
                              void* d_out, int out_size) {
    const int*   batch_user = (const int*)  d_in[0];
    const int*   batch_pos  = (const int*)  d_in[1];
    const int*   batch_neg  = (const int*)  d_in[2];
    const float* embed_user = (const float*)d_in[3];
    const float* embed_item = (const float*)d_in[4];
    const int*   row_idx    = (const int*)  d_in[5];
    const int*   col_idx    = (const int*)  d_in[6];
    const float* a_vals     = (const float*)d_in[7];
    float* out = (float*)d_out;

    uint4 *E0, *E1, *E2;
    void* cntp = nullptr;
    cudaGetSymbolAddress((void**)&E0, g_E0h);
    cudaGetSymbolAddress((void**)&E1, g_E1h);
    cudaGetSymbolAddress((void**)&E2, g_E2h);
    cudaGetSymbolAddress(&cntp, g_cnt);

    const int T = 256;
    const int buildBlocks = (NQ + T - 1) / T;                   // 3907: 1 quad/thread
    const int csrBlocks   = (N_NODES * 32 + SPMM_T - 1) / SPMM_T;
    const int lastBlocks  = (3 * BATCH * 32 + T - 1) / T;

    cudaMemsetAsync(cntp, 0, N_NODES * sizeof(int));

    // fused: E0 fp16 conversion + histogram + bucket scatter (one pass)
    lgcn_init_build<<<buildBlocks, T>>>((const float2*)embed_user,
                                        (const float2*)embed_item,
                                        row_idx, col_idx, a_vals);

    // layers 1 and 2 over all nodes
    lgcn_csr<<<csrBlocks, SPMM_T>>>(E0, E1);
    lgcn_csr<<<csrBlocks, SPMM_T>>>(E1, E2);

    // fused layer 3 + accumulate + gather over the 12k batch rows only
    lgcn_last<<<lastBlocks, T>>>(batch_user, batch_pos, batch_neg,
                                 (float4*)out);
}

// round 16
// speedup vs baseline: 1.3901x; 1.0023x over previous
#include <cuda_runtime.h>
#include <cuda_fp16.h>

#define N_USERS 100000
#define N_ITEMS 50000
#define N_NODES 150000  // N_USERS + N_ITEMS
#define EMBED   64
#define NNZ     4000000
#define BATCH   4096
#define ROW2    32            // EMBED floats = 32 float2
#define TOTAL2  (N_NODES * ROW2)
#define NQ      (NNZ >> 2)    // 1M edge quads

// Edge packing: bits[0:18) = col (N_NODES < 2^18), bits[18:32) = a as
// 14-bit fixed point in [0,1]. |quant err| <= 3.05e-5 absolute.
#define COL_MASK 0x3FFFFu
#define A_SCALE  16383.0f
#define A_INV    (1.0f / 16383.0f)

// Padded bucket capacity: degrees ~ Poisson(26.7), max over 150k nodes ~52.
#define CAP_LG 6              // 64 slots * 4B = 256B per node bucket
#define CAP    (1 << CAP_LG)

// ---------------------------------------------------------------------------
// Device-global scratch. Three fp16 layer tables; layer 3 is computed only
// at the 12k batch rows, fused into the final gather (fp32 path).
// ---------------------------------------------------------------------------
__device__ __half g_E0h[N_NODES * EMBED];
__device__ __half g_E1h[N_NODES * EMBED];
__device__ __half g_E2h[N_NODES * EMBED];

__device__ int      g_cnt[N_NODES];            // degree / slot cursor
__device__ unsigned g_ebuck[N_NODES * CAP];    // packed (col|a14) buckets

// ---------------------------------------------------------------------------
// Fused init + build: E0h = fp16(concat(eu, ei));
// per edge: k = cnt[r]++ ; bucket[r*CAP + k] = pack(col, a).
// ---------------------------------------------------------------------------
__global__ void lgcn_init_build(const float2* __restrict__ eu,
                                const float2* __restrict__ ei,
                                const int* __restrict__ row,
                                const int* __restrict__ col,
                                const float* __restrict__ a) {
    half2* E0h2 = reinterpret_cast<half2*>(g_E0h);
    const int stride = gridDim.x * blockDim.x;
    const int gid = blockIdx.x * blockDim.x + threadIdx.x;
    const int user2 = N_USERS * ROW2;
    for (int i = gid; i < TOTAL2; i += stride) {
        float2 v = (i < user2) ? eu[i] : ei[i - user2];
        E0h2[i] = __float22half2_rn(v);
    }
    if (gid < NQ) {
        const int4*   row4 = reinterpret_cast<const int4*>(row);
        const int4*   col4 = reinterpret_cast<const int4*>(col);
        const float4* a4   = reinterpret_cast<const float4*>(a);
        int4   r = __ldg(row4 + gid);
        int4   c = __ldg(col4 + gid);
        float4 w = __ldg(a4 + gid);
        unsigned p0 = (unsigned)c.x | (__float2uint_rn(w.x * A_SCALE) << 18);
        unsigned p1 = (unsigned)c.y | (__float2uint_rn(w.y * A_SCALE) << 18);
        unsigned p2 = (unsigned)c.z | (__float2uint_rn(w.z * A_SCALE) << 18);
        unsigned p3 = (unsigned)c.w | (__float2uint_rn(w.w * A_SCALE) << 18);
        int k0 = atomicAdd(&g_cnt[r.x], 1);
        int k1 = atomicAdd(&g_cnt[r.y], 1);
        int k2 = atomicAdd(&g_cnt[r.z], 1);
        int k3 = atomicAdd(&g_cnt[r.w], 1);
        g_ebuck[((size_t)r.x << CAP_LG) + k0] = p0;
        g_ebuck[((size_t)r.y << CAP_LG) + k1] = p1;
        g_ebuck[((size_t)r.z << CAP_LG) + k2] = p2;
        g_ebuck[((size_t)r.w << CAP_LG) + k3] = p3;
    }
}

// ---------------------------------------------------------------------------
// Bucket SpMM, fp16 in/out, fp32 math, 2-DEEP software pipeline:
// two edge quads (e0, e1) are always in flight ahead of the gather, so two
// independent gathers can overlap even across the edge-load dependence.
// One warp per node; eg = lane>>3 picks the edge of the quad; 8 lanes × 16B
// cover the 128B row.
// ---------------------------------------------------------------------------
#define SPMM_T 256
__global__ void lgcn_csr(const uint4* __restrict__ src,
                         uint4* __restrict__ dst) {
    const int warp = (blockIdx.x * SPMM_T + threadIdx.x) >> 5;
    const int lane = threadIdx.x & 31;
    if (warp >= N_NODES) return;
    const unsigned* eb = g_ebuck + ((size_t)warp << CAP_LG);
    const int n  = __ldg(&g_cnt[warp]);
    const int eg = lane >> 3;          // 0..3: which edge of the quad
    const int l8 = lane & 7;           // 16B chunk within the 128B row

    float2 s0 = make_float2(0.f, 0.f), s1 = s0, s2 = s0, s3 = s0;
    unsigned e0 = (eg     < n) ? __ldg(eb + eg)     : 0u;
    unsigned e1 = (4 + eg < n) ? __ldg(eb + 4 + eg) : 0u;
    #pragma unroll 2
    for (int base = 0; base < n; base += 4) {
        const int nidx = base + 8 + eg;
        unsigned e2 = (nidx < n) ? __ldg(eb + nidx) : 0u;
        const float av = (float)(e0 >> 18) * A_INV;
        uint4 h = __ldg(src + ((size_t)(e0 & COL_MASK) << 3) + l8);
        float2 v0 = __half22float2(*reinterpret_cast<half2*>(&h.x));
        float2 v1 = __half22float2(*reinterpret_cast<half2*>(&h.y));
        float2 v2 = __half22float2(*reinterpret_cast<half2*>(&h.z));
        float2 v3 = __half22float2(*reinterpret_cast<half2*>(&h.w));
        s0.x += av * v0.x; s0.y += av * v0.y;
        s1.x += av * v1.x; s1.y += av * v1.y;
        s2.x += av * v2.x; s2.y += av * v2.y;
        s3.x += av * v3.x; s3.y += av * v3.y;
        e0 = e1;
        e1 = e2;
    }
    // combine the 4 edge-groups (lanes with equal l8)
    #pragma unroll
    for (int d = 8; d <= 16; d <<= 1) {
        s0.x += __shfl_xor_sync(0xffffffffu, s0.x, d);
        s0.y += __shfl_xor_sync(0xffffffffu, s0.y, d);
        s1.x += __shfl_xor_sync(0xffffffffu, s1.x, d);
        s1.y += __shfl_xor_sync(0xffffffffu, s1.y, d);
        s2.x += __shfl_xor_sync(0xffffffffu, s2.x, d);
        s2.y += __shfl_xor_sync(0xffffffffu, s2.y, d);
        s3.x += __shfl_xor_sync(0xffffffffu, s3.x, d);
        s3.y += __shfl_xor_sync(0xffffffffu, s3.y, d);
    }
    if (eg == 0) {
        half2 p0 = __floats2half2_rn(s0.x, s0.y);
        half2 p1 = __floats2half2_rn(s1.x, s1.y);
        half2 p2 = __floats2half2_rn(s2.x, s2.y);
        half2 p3 = __floats2half2_rn(s3.x, s3.y);
        uint4 o;
        o.x = *reinterpret_cast<unsigned*>(&p0);
        o.y = *reinterpret_cast<unsigned*>(&p1);
        o.z = *reinterpret_cast<unsigned*>(&p2);
        o.w = *reinterpret_cast<unsigned*>(&p3);
        dst[((size_t)warp << 3) + l8] = o;
    }
}

// ---------------------------------------------------------------------------
// Fused layer-3 + gather, TWO warps per output row (even/odd edge quads)
// combined via smem — halves each warp's sequential chain and doubles the
// warp count to hide L2 latency in this short tail kernel.
//   e3 = sum_j a[j] * E2[col[j]]   (fp32, never quantized to fp16)
//   out[r] = 0.25 * ((E0+E1+E2)[node] + e3)
// Grid is sized EXACTLY (3*BATCH rows * 2 warps), so no early returns.
// ---------------------------------------------------------------------------
#define LAST_T 256   // 8 warps = 4 row-pairs per block
__global__ void lgcn_last(const int* __restrict__ bu,
                          const int* __restrict__ bp,
                          const int* __restrict__ bn,
                          float4* __restrict__ out) {
    __shared__ float4 sp[4][8][2];   // [local pair][l8][s01 / s23]
    const int gw    = (blockIdx.x * LAST_T + threadIdx.x) >> 5;
    const int lane  = threadIdx.x & 31;
    const int rrow  = gw >> 1;              // output row 0 .. 3*BATCH-1
    const int hhalf = gw & 1;               // 0: even quads, 1: odd quads
    const int lpair = threadIdx.x >> 6;     // local row-pair 0..3

    const int which = rrow / BATCH;
    const int b     = rrow - which * BATCH;
    int node;
    if (which == 0)      node = __ldg(bu + b);
    else if (which == 1) node = N_USERS + __ldg(bp + b);
    else                 node = N_USERS + __ldg(bn + b);

    const unsigned* eb = g_ebuck + ((size_t)node << CAP_LG);
    const int n  = __ldg(&g_cnt[node]);
    const int eg = lane >> 3;
    const int l8 = lane & 7;

    const uint4* E2 = reinterpret_cast<const uint4*>(g_E2h);
    float2 s0 = make_float2(0.f, 0.f), s1 = s0, s2 = s0, s3 = s0;
    const int start = hhalf * 4 + eg;
    unsigned e_cur = (start < n) ? __ldg(eb + start) : 0u;
    for (int base = hhalf * 4; base < n; base += 8) {
        const int nidx = base + 8 + eg;
        unsigned e_next = (nidx < n) ? __ldg(eb + nidx) : 0u;
        const float av = (float)(e_cur >> 18) * A_INV;
        uint4 h = __ldg(E2 + ((size_t)(e_cur & COL_MASK) << 3) + l8);
        float2 v0 = __half22float2(*reinterpret_cast<half2*>(&h.x));
        float2 v1 = __half22float2(*reinterpret_cast<half2*>(&h.y));
        float2 v2 = __half22float2(*reinterpret_cast<half2*>(&h.z));
        float2 v3 = __half22float2(*reinterpret_cast<half2*>(&h.w));
        s0.x += av * v0.x; s0.y += av * v0.y;
        s1.x += av * v1.x; s1.y += av * v1.y;
        s2.x += av * v2.x; s2.y += av * v2.y;
        s3.x += av * v3.x; s3.y += av * v3.y;
        e_cur = e_next;
    }
    #pragma unroll
    for (int d = 8; d <= 16; d <<= 1) {
        s0.x += __shfl_xor_sync(0xffffffffu, s0.x, d);
        s0.y += __shfl_xor_sync(0xffffffffu, s0.y, d);
        s1.x += __shfl_xor_sync(0xffffffffu, s1.x, d);
        s1.y += __shfl_xor_sync(0xffffffffu, s1.y, d);
        s2.x += __shfl_xor_sync(0xffffffffu, s2.x, d);
        s2.y += __shfl_xor_sync(0xffffffffu, s2.y, d);
        s3.x += __shfl_xor_sync(0xffffffffu, s3.x, d);
        s3.y += __shfl_xor_sync(0xffffffffu, s3.y, d);
    }
    // odd-half warp publishes its partial
    if (hhalf == 1 && lane < 8) {
        sp[lpair][l8][0] = make_float4(s0.x, s0.y, s1.x, s1.y);
        sp[lpair][l8][1] = make_float4(s2.x, s2.y, s3.x, s3.y);
    }
    __syncthreads();
    // even-half warp combines, adds E0+E1+E2 at node, writes fp32 out
    if (hhalf == 0 && lane < 8) {
        float4 q0 = sp[lpair][l8][0];
        float4 q1 = sp[lpair][l8][1];
        s0.x += q0.x; s0.y += q0.y; s1.x += q0.z; s1.y += q0.w;
        s2.x += q1.x; s2.y += q1.y; s3.x += q1.z; s3.y += q1.w;
        const size_t o = ((size_t)node << 3) + l8;
        const uint4* tabs[3] = {
            reinterpret_cast<const uint4*>(g_E0h),
            reinterpret_cast<const uint4*>(g_E1h),
            reinterpret_cast<const uint4*>(g_E2h)
        };
        #pragma unroll
        for (int t = 0; t < 3; t++) {
            uint4 h = __ldg(tabs[t] + o);
            float2 v0 = __half22float2(*reinterpret_cast<half2*>(&h.x));
            float2 v1 = __half22float2(*reinterpret_cast<half2*>(&h.y));
            float2 v2 = __half22float2(*reinterpret_cast<half2*>(&h.z));
            float2 v3 = __half22float2(*reinterpret_cast<half2*>(&h.w));
            s0.x += v0.x; s0.y += v0.y;
            s1.x += v1.x; s1.y += v1.y;
            s2.x += v2.x; s2.y += v2.y;
            s3.x += v3.x; s3.y += v3.y;
        }
        const float sc = 0.25f;   // 1/(N_LAYERS+1)
        float4* orow = out + ((size_t)rrow << 4) + l8 * 2;
        orow[0] = make_float4(s0.x * sc, s0.y * sc, s1.x * sc, s1.y * sc);
        orow[1] = make_float4(s2.x * sc, s2.y * sc, s3.x * sc, s3.y * sc);
    }
}

// ---------------------------------------------------------------------------
// launch
// ---------------------------------------------------------------------------
extern "C" void kernel_launch(void* const* d_in, const int* in_sizes, int n_in,
                              void* d_out, int out_size) {
    const int*   batch_user = (const int*)  d_in[0];
    const int*   batch_pos  = (const int*)  d_in[1];
    const int*   batch_neg  = (const int*)  d_in[2];
    const float* embed_user = (const float*)d_in[3];
    const float* embed_item = (const float*)d_in[4];
    const int*   row_idx    = (const int*)  d_in[5];
    const int*   col_idx    = (const int*)  d_in[6];
    const float* a_vals     = (const float*)d_in[7];
    float* out = (float*)d_out;

    uint4 *E0, *E1, *E2;
    void* cntp = nullptr;
    cudaGetSymbolAddress((void**)&E0, g_E0h);
    cudaGetSymbolAddress((void**)&E1, g_E1h);
    cudaGetSymbolAddress((void**)&E2, g_E2h);
    cudaGetSymbolAddress(&cntp, g_cnt);

    const int T = 256;
    const int buildBlocks = (NQ + T - 1) / T;                   // 3907: 1 quad/thread
    const int csrBlocks   = (N_NODES * 32 + SPMM_T - 1) / SPMM_T;
    const int lastBlocks  = (3 * BATCH * 2 * 32) / LAST_T;      // 3072, exact

    cudaMemsetAsync(cntp, 0, N_NODES * sizeof(int));

    // fused: E0 fp16 conversion + histogram + bucket scatter (one pass)
    lgcn_init_build<<<buildBlocks, T>>>((const float2*)embed_user,
                                        (const float2*)embed_item,
                                        row_idx, col_idx, a_vals);

    // layers 1 and 2 over all nodes
    lgcn_csr<<<csrBlocks, SPMM_T>>>(E0, E1);
    lgcn_csr<<<csrBlocks, SPMM_T>>>(E1, E2);

    // fused layer 3 + accumulate + gather over the 12k batch rows only
    lgcn_last<<<lastBlocks, LAST_T>>>(batch_user, batch_pos, batch_neg,
                                      (float4*)out);
}

// round 17
// speedup vs baseline: 1.4224x; 1.0232x over previous
#include <cuda_runtime.h>
#include <cuda_fp16.h>

#define N_USERS 100000
#define N_ITEMS 50000
#define N_NODES 150000  // N_USERS + N_ITEMS
#define EMBED   64
#define NNZ     4000000
#define BATCH   4096
#define ROW2    32            // EMBED floats = 32 float2
#define TOTAL2  (N_NODES * ROW2)
#define NQ      (NNZ >> 2)    // 1M edge quads

// Edge packing: bits[0:18) = col (N_NODES < 2^18), bits[18:32) = a as
// 14-bit fixed point in [0,1]. |quant err| <= 3.05e-5 absolute.
#define COL_MASK 0x3FFFFu
#define A_SCALE  16383.0f
#define A_INV    (1.0f / 16383.0f)

// Padded bucket capacity: degrees ~ Poisson(26.7), max over 150k nodes ~52.
#define CAP_LG 6              // 64 slots * 4B = 256B per node bucket
#define CAP    (1 << CAP_LG)

// ---------------------------------------------------------------------------
// Device-global scratch. Three fp16 layer tables; layer 3 is computed only
// at the 12k batch rows, fused into the final gather (fp32 path).
// ---------------------------------------------------------------------------
__device__ __half g_E0h[N_NODES * EMBED];
__device__ __half g_E1h[N_NODES * EMBED];
__device__ __half g_E2h[N_NODES * EMBED];

__device__ int      g_cnt[N_NODES];            // degree / slot cursor
__device__ unsigned g_ebuck[N_NODES * CAP];    // packed (col|a14) buckets

// ---------------------------------------------------------------------------
// Fused init + build: E0h = fp16(concat(eu, ei));
// per edge: k = cnt[r]++ ; bucket[r*CAP + k] = pack(col, a).
// ---------------------------------------------------------------------------
__global__ void lgcn_init_build(const float2* __restrict__ eu,
                                const float2* __restrict__ ei,
                                const int* __restrict__ row,
                                const int* __restrict__ col,
                                const float* __restrict__ a) {
    half2* E0h2 = reinterpret_cast<half2*>(g_E0h);
    const int stride = gridDim.x * blockDim.x;
    const int gid = blockIdx.x * blockDim.x + threadIdx.x;
    const int user2 = N_USERS * ROW2;
    for (int i = gid; i < TOTAL2; i += stride) {
        float2 v = (i < user2) ? eu[i] : ei[i - user2];
        E0h2[i] = __float22half2_rn(v);
    }
    if (gid < NQ) {
        const int4*   row4 = reinterpret_cast<const int4*>(row);
        const int4*   col4 = reinterpret_cast<const int4*>(col);
        const float4* a4   = reinterpret_cast<const float4*>(a);
        int4   r = __ldg(row4 + gid);
        int4   c = __ldg(col4 + gid);
        float4 w = __ldg(a4 + gid);
        unsigned p0 = (unsigned)c.x | (__float2uint_rn(w.x * A_SCALE) << 18);
        unsigned p1 = (unsigned)c.y | (__float2uint_rn(w.y * A_SCALE) << 18);
        unsigned p2 = (unsigned)c.z | (__float2uint_rn(w.z * A_SCALE) << 18);
        unsigned p3 = (unsigned)c.w | (__float2uint_rn(w.w * A_SCALE) << 18);
        int k0 = atomicAdd(&g_cnt[r.x], 1);
        int k1 = atomicAdd(&g_cnt[r.y], 1);
        int k2 = atomicAdd(&g_cnt[r.z], 1);
        int k3 = atomicAdd(&g_cnt[r.w], 1);
        g_ebuck[((size_t)r.x << CAP_LG) + k0] = p0;
        g_ebuck[((size_t)r.y << CAP_LG) + k1] = p1;
        g_ebuck[((size_t)r.z << CAP_LG) + k2] = p2;
        g_ebuck[((size_t)r.w << CAP_LG) + k3] = p3;
    }
}

// ---------------------------------------------------------------------------
// Bucket SpMM, fp16 in/out, fp32 math, 2-DEEP software pipeline (proven in
// R16): two edge quads always in flight ahead of the gather. One warp per
// node; eg = lane>>3 picks the edge; 8 lanes × 16B cover the 128B row.
// ---------------------------------------------------------------------------
#define SPMM_T 256
__global__ void lgcn_csr(const uint4* __restrict__ src,
                         uint4* __restrict__ dst) {
    const int warp = (blockIdx.x * SPMM_T + threadIdx.x) >> 5;
    const int lane = threadIdx.x & 31;
    if (warp >= N_NODES) return;
    const unsigned* eb = g_ebuck + ((size_t)warp << CAP_LG);
    const int n  = __ldg(&g_cnt[warp]);
    const int eg = lane >> 3;          // 0..3: which edge of the quad
    const int l8 = lane & 7;           // 16B chunk within the 128B row

    float2 s0 = make_float2(0.f, 0.f), s1 = s0, s2 = s0, s3 = s0;
    unsigned e0 = (eg     < n) ? __ldg(eb + eg)     : 0u;
    unsigned e1 = (4 + eg < n) ? __ldg(eb + 4 + eg) : 0u;
    #pragma unroll 2
    for (int base = 0; base < n; base += 4) {
        const int nidx = base + 8 + eg;
        unsigned e2 = (nidx < n) ? __ldg(eb + nidx) : 0u;
        const float av = (float)(e0 >> 18) * A_INV;
        uint4 h = __ldg(src + ((size_t)(e0 & COL_MASK) << 3) + l8);
        float2 v0 = __half22float2(*reinterpret_cast<half2*>(&h.x));
        float2 v1 = __half22float2(*reinterpret_cast<half2*>(&h.y));
        float2 v2 = __half22float2(*reinterpret_cast<half2*>(&h.z));
        float2 v3 = __half22float2(*reinterpret_cast<half2*>(&h.w));
        s0.x += av * v0.x; s0.y += av * v0.y;
        s1.x += av * v1.x; s1.y += av * v1.y;
        s2.x += av * v2.x; s2.y += av * v2.y;
        s3.x += av * v3.x; s3.y += av * v3.y;
        e0 = e1;
        e1 = e2;
    }
    // combine the 4 edge-groups (lanes with equal l8)
    #pragma unroll
    for (int d = 8; d <= 16; d <<= 1) {
        s0.x += __shfl_xor_sync(0xffffffffu, s0.x, d);
        s0.y += __shfl_xor_sync(0xffffffffu, s0.y, d);
        s1.x += __shfl_xor_sync(0xffffffffu, s1.x, d);
        s1.y += __shfl_xor_sync(0xffffffffu, s1.y, d);
        s2.x += __shfl_xor_sync(0xffffffffu, s2.x, d);
        s2.y += __shfl_xor_sync(0xffffffffu, s2.y, d);
        s3.x += __shfl_xor_sync(0xffffffffu, s3.x, d);
        s3.y += __shfl_xor_sync(0xffffffffu, s3.y, d);
    }
    if (eg == 0) {
        half2 p0 = __floats2half2_rn(s0.x, s0.y);
        half2 p1 = __floats2half2_rn(s1.x, s1.y);
        half2 p2 = __floats2half2_rn(s2.x, s2.y);
        half2 p3 = __floats2half2_rn(s3.x, s3.y);
        uint4 o;
        o.x = *reinterpret_cast<unsigned*>(&p0);
        o.y = *reinterpret_cast<unsigned*>(&p1);
        o.z = *reinterpret_cast<unsigned*>(&p2);
        o.w = *reinterpret_cast<unsigned*>(&p3);
        dst[((size_t)warp << 3) + l8] = o;
    }
}

// ---------------------------------------------------------------------------
// Fused layer-3 + gather: ONE warp per output row (R15 structure — the
// 2-warp smem split regressed), with the 2-deep edge pipeline applied.
//   e3 = sum_j a[j] * E2[col[j]]   (fp32, never quantized to fp16)
//   out[r] = 0.25 * ((E0+E1+E2)[node] + e3)
// ---------------------------------------------------------------------------
__global__ void lgcn_last(const int* __restrict__ bu,
                          const int* __restrict__ bp,
                          const int* __restrict__ bn,
                          float4* __restrict__ out) {
    const int warp = (blockIdx.x * blockDim.x + threadIdx.x) >> 5;
    const int lane = threadIdx.x & 31;
    if (warp >= 3 * BATCH) return;
    const int which = warp / BATCH;
    const int b     = warp - which * BATCH;
    int node;
    if (which == 0)      node = __ldg(bu + b);
    else if (which == 1) node = N_USERS + __ldg(bp + b);
    else                 node = N_USERS + __ldg(bn + b);

    const unsigned* eb = g_ebuck + ((size_t)node << CAP_LG);
    const int n  = __ldg(&g_cnt[node]);
    const int eg = lane >> 3;
    const int l8 = lane & 7;

    const uint4* E2 = reinterpret_cast<const uint4*>(g_E2h);
    float2 s0 = make_float2(0.f, 0.f), s1 = s0, s2 = s0, s3 = s0;
    unsigned e0 = (eg     < n) ? __ldg(eb + eg)     : 0u;
    unsigned e1 = (4 + eg < n) ? __ldg(eb + 4 + eg) : 0u;
    for (int base = 0; base < n; base += 4) {
        const int nidx = base + 8 + eg;
        unsigned e2 = (nidx < n) ? __ldg(eb + nidx) : 0u;
        const float av = (float)(e0 >> 18) * A_INV;
        uint4 h = __ldg(E2 + ((size_t)(e0 & COL_MASK) << 3) + l8);
        float2 v0 = __half22float2(*reinterpret_cast<half2*>(&h.x));
        float2 v1 = __half22float2(*reinterpret_cast<half2*>(&h.y));
        float2 v2 = __half22float2(*reinterpret_cast<half2*>(&h.z));
        float2 v3 = __half22float2(*reinterpret_cast<half2*>(&h.w));
        s0.x += av * v0.x; s0.y += av * v0.y;
        s1.x += av * v1.x; s1.y += av * v1.y;
        s2.x += av * v2.x; s2.y += av * v2.y;
        s3.x += av * v3.x; s3.y += av * v3.y;
        e0 = e1;
        e1 = e2;
    }
    #pragma unroll
    for (int d = 8; d <= 16; d <<= 1) {
        s0.x += __shfl_xor_sync(0xffffffffu, s0.x, d);
        s0.y += __shfl_xor_sync(0xffffffffu, s0.y, d);
        s1.x += __shfl_xor_sync(0xffffffffu, s1.x, d);
        s1.y += __shfl_xor_sync(0xffffffffu, s1.y, d);
        s2.x += __shfl_xor_sync(0xffffffffu, s2.x, d);
        s2.y += __shfl_xor_sync(0xffffffffu, s2.y, d);
        s3.x += __shfl_xor_sync(0xffffffffu, s3.x, d);
        s3.y += __shfl_xor_sync(0xffffffffu, s3.y, d);
    }
    if (eg == 0) {
        const size_t o = ((size_t)node << 3) + l8;
        const uint4* tabs[3] = {
            reinterpret_cast<const uint4*>(g_E0h),
            reinterpret_cast<const uint4*>(g_E1h),
            reinterpret_cast<const uint4*>(g_E2h)
        };
        #pragma unroll
        for (int t = 0; t < 3; t++) {
            uint4 h = __ldg(tabs[t] + o);
            float2 v0 = __half22float2(*reinterpret_cast<half2*>(&h.x));
            float2 v1 = __half22float2(*reinterpret_cast<half2*>(&h.y));
            float2 v2 = __half22float2(*reinterpret_cast<half2*>(&h.z));
            float2 v3 = __half22float2(*reinterpret_cast<half2*>(&h.w));
            s0.x += v0.x; s0.y += v0.y;
            s1.x += v1.x; s1.y += v1.y;
            s2.x += v2.x; s2.y += v2.y;
            s3.x += v3.x; s3.y += v3.y;
        }
        const float sc = 0.25f;   // 1/(N_LAYERS+1)
        float4* orow = out + ((size_t)warp << 4) + l8 * 2;
        orow[0] = make_float4(s0.x * sc, s0.y * sc, s1.x * sc, s1.y * sc);
        orow[1] = make_float4(s2.x * sc, s2.y * sc, s3.x * sc, s3.y * sc);
    }
}

// ---------------------------------------------------------------------------
// launch
// ---------------------------------------------------------------------------
extern "C" void kernel_launch(void* const* d_in, const int* in_sizes, int n_in,
                              void* d_out, int out_size) {
    const int*   batch_user = (const int*)  d_in[0];
    const int*   batch_pos  = (const int*)  d_in[1];
    const int*   batch_neg  = (const int*)  d_in[2];
    const float* embed_user = (const float*)d_in[3];
    const float* embed_item = (const float*)d_in[4];
    const int*   row_idx    = (const int*)  d_in[5];
    const int*   col_idx    = (const int*)  d_in[6];
    const float* a_vals     = (const float*)d_in[7];
    float* out = (float*)d_out;

    uint4 *E0, *E1, *E2;
    void* cntp = nullptr;
    cudaGetSymbolAddress((void**)&E0, g_E0h);
    cudaGetSymbolAddress((void**)&E1, g_E1h);
    cudaGetSymbolAddress((void**)&E2, g_E2h);
    cudaGetSymbolAddress(&cntp, g_cnt);

    const int T = 256;
    const int buildBlocks = (NQ + T - 1) / T;                   // 3907: 1 quad/thread
    const int csrBlocks   = (N_NODES * 32 + SPMM_T - 1) / SPMM_T;
    const int lastBlocks  = (3 * BATCH * 32 + T - 1) / T;

    cudaMemsetAsync(cntp, 0, N_NODES * sizeof(int));

    // fused: E0 fp16 conversion + histogram + bucket scatter (one pass)
    lgcn_init_build<<<buildBlocks, T>>>((const float2*)embed_user,
                                        (const float2*)embed_item,
                                        row_idx, col_idx, a_vals);

    // layers 1 and 2 over all nodes
    lgcn_csr<<<csrBlocks, SPMM_T>>>(E0, E1);
    lgcn_csr<<<csrBlocks, SPMM_T>>>(E1, E2);

    // fused layer 3 + accumulate + gather over the 12k batch rows only
    lgcn_last<<<lastBlocks, T>>>(batch_user, batch_pos, batch_neg,
                                 (float4*)out);
}